// round 1
// baseline (speedup 1.0000x reference)
#include <cuda_runtime.h>
#include <cstdint>

// ---- problem constants (match reference) ----
#define BB 4
#define HH 128
#define WW 128
#define SS 72
#define SPS 24          // slices per stack
#define ZS 120          // z_scale
#define ZV 122          // padded depth
#define ST_RATIO 5.0f

#define VOXELS (BB * HH * WW * ZV)      // 7,995,392
#define PIXELS (BB * HH * WW * SS)      // 4,718,592
#define OUT_PER (BB * HH * WW * ZS)     // 7,864,320

// Interleaved scratch: [2*lin] = N accumulator, [2*lin+1] = D accumulator.
__device__ float g_acc[2 * VOXELS];     // ~64 MB, fits in L2

// ---------------------------------------------------------------------------
// Splat kernel: one thread per (b,h,w,s) pixel, s fastest (coalesced vol read).
// ---------------------------------------------------------------------------
__global__ __launch_bounds__(256) void splat_kernel(
    const float* __restrict__ vol,   // (B,H,W,S,1) — linear index == thread index
    const float* __restrict__ trf)   // (B,S,3,4)
{
    int i = blockIdx.x * blockDim.x + threadIdx.x;
    if (i >= PIXELS) return;

    int s = i % SS;
    int rem = i / SS;
    int w = rem % WW;
    rem /= WW;
    int h = rem % HH;
    int b = rem / HH;

    float v = vol[i];

    const float* Ap = trf + (size_t)(b * SS + s) * 12;
    // A = trf + eye(4)[:3,:]
    float A00 = Ap[0] + 1.0f, A01 = Ap[1],        A02 = Ap[2],        A03 = Ap[3];
    float A10 = Ap[4],        A11 = Ap[5] + 1.0f, A12 = Ap[6],        A13 = Ap[7];
    float A20 = Ap[8],        A21 = Ap[9],        A22 = Ap[10] + 1.0f, A23 = Ap[11];

    int o = s / SPS;                       // 0=axi, 1=cor, 2=sag
    float t = (float)(s % SPS) * ST_RATIO;

    float bx, by, bz;
    if (o == 0)      { bx = (float)h; by = (float)w; bz = t; }
    else if (o == 1) { bx = (float)h; by = t;        bz = (float)w; }
    else             { bx = t;        by = (float)h; bz = (float)w; }

    float x = A00 * bx + A01 * by + A02 * bz + A03;
    float y = A10 * bx + A11 * by + A12 * bz + A13;
    float z = A20 * bx + A21 * by + A22 * bz + A23 + 1.0f;   // +1 pad offset

    float x0f = floorf(x), y0f = floorf(y), z0f = floorf(z);
    float wx = x - x0f, wy = y - y0f, wz = z - z0f;
    int x0 = (int)x0f, y0 = (int)y0f, z0 = (int)z0f;

    int base_b = b * HH;

    #pragma unroll
    for (int dx = 0; dx < 2; dx++) {
        int xi = x0 + dx;
        if (xi < 0 || xi >= HH) continue;
        float fwx = dx ? wx : (1.0f - wx);
        #pragma unroll
        for (int dy = 0; dy < 2; dy++) {
            int yi = y0 + dy;
            if (yi < 0 || yi >= WW) continue;
            float fwy = dy ? wy : (1.0f - wy);
            float fwxy = fwx * fwy;
            int lin_xy = ((base_b + xi) * WW + yi) * ZV;
            #pragma unroll
            for (int dz = 0; dz < 2; dz++) {
                int zi = z0 + dz;
                if (zi < 0 || zi >= ZV) continue;
                float ww = fwxy * (dz ? wz : (1.0f - wz));
                int lin = lin_xy + zi;
                atomicAdd(&g_acc[2 * lin],     ww * v);
                atomicAdd(&g_acc[2 * lin + 1], ww);
            }
        }
    }
}

// ---------------------------------------------------------------------------
// Finalize: crop z[1:1+ZS], split interleaved N/D, apply where(D<=0, 1, D).
// Output layout: N block (B,H,W,ZS) then D block (B,H,W,ZS).
// ---------------------------------------------------------------------------
__global__ __launch_bounds__(256) void finalize_kernel(float* __restrict__ out)
{
    int j = blockIdx.x * blockDim.x + threadIdx.x;
    if (j >= OUT_PER) return;

    int z = j % ZS;
    int hwb = j / ZS;                 // (b*H+h)*W + w
    int lin = hwb * ZV + (z + 1);

    float n = g_acc[2 * lin];
    float d = g_acc[2 * lin + 1];

    out[j]           = n;
    out[OUT_PER + j] = (d > 0.0f) ? d : 1.0f;
}

// ---------------------------------------------------------------------------
extern "C" void kernel_launch(void* const* d_in, const int* in_sizes, int n_in,
                              void* d_out, int out_size)
{
    const float* vol = (const float*)d_in[0];
    const float* trf = (const float*)d_in[1];
    float* out = (float*)d_out;

    void* acc_ptr = nullptr;
    cudaGetSymbolAddress(&acc_ptr, g_acc);
    cudaMemsetAsync(acc_ptr, 0, sizeof(float) * 2 * VOXELS, 0);

    {
        int threads = 256;
        int blocks = (PIXELS + threads - 1) / threads;
        splat_kernel<<<blocks, threads>>>(vol, trf);
    }
    {
        int threads = 256;
        int blocks = (OUT_PER + threads - 1) / threads;
        finalize_kernel<<<blocks, threads>>>(out);
    }
}

// round 2
// speedup vs baseline: 1.8583x; 1.8583x over previous
#include <cuda_runtime.h>
#include <cstdint>

// ---- problem constants (match reference) ----
#define BB 4
#define HH 128
#define WW 128
#define SS 72
#define SPS 24          // slices per stack
#define ZS 120          // z_scale
#define ZV 122          // padded depth
#define ST_RATIO 5.0f

#define VOXELS (BB * HH * WW * ZV)      // 7,995,392
#define PIXELS (BB * HH * WW * SS)      // 4,718,592
#define OUT_PER (BB * HH * WW * ZS)     // 7,864,320

// Interleaved scratch: [2*lin] = N accumulator, [2*lin+1] = D accumulator.
// 8-byte aligned pairs -> one red.global.add.v2.f32 per corner.
__device__ __align__(16) float g_acc[2 * VOXELS];     // ~64 MB, fits in L2

__device__ __forceinline__ void red_add_v2(float* p, float a, float b) {
    // vector reduction (sm_90+): adds {a,b} to the 8B-aligned pair at p
    asm volatile("red.global.add.v2.f32 [%0], {%1, %2};"
                 :: "l"(p), "f"(a), "f"(b) : "memory");
}

// ---------------------------------------------------------------------------
// Splat kernel: one thread per (b,h,w,s) pixel, s fastest (coalesced vol read).
// ---------------------------------------------------------------------------
__global__ __launch_bounds__(256) void splat_kernel(
    const float* __restrict__ vol,   // (B,H,W,S,1) — linear index == thread index
    const float* __restrict__ trf)   // (B,S,3,4)
{
    int i = blockIdx.x * blockDim.x + threadIdx.x;
    if (i >= PIXELS) return;

    int s = i % SS;
    int rem = i / SS;
    int w = rem % WW;
    rem /= WW;
    int h = rem % HH;
    int b = rem / HH;

    float v = vol[i];

    const float* Ap = trf + (size_t)(b * SS + s) * 12;
    // A = trf + eye(4)[:3,:]
    float A00 = Ap[0] + 1.0f, A01 = Ap[1],        A02 = Ap[2],         A03 = Ap[3];
    float A10 = Ap[4],        A11 = Ap[5] + 1.0f, A12 = Ap[6],         A13 = Ap[7];
    float A20 = Ap[8],        A21 = Ap[9],        A22 = Ap[10] + 1.0f, A23 = Ap[11];

    int o = s / SPS;                       // 0=axi, 1=cor, 2=sag
    float t = (float)(s % SPS) * ST_RATIO;

    float bx, by, bz;
    if (o == 0)      { bx = (float)h; by = (float)w; bz = t; }
    else if (o == 1) { bx = (float)h; by = t;        bz = (float)w; }
    else             { bx = t;        by = (float)h; bz = (float)w; }

    float x = A00 * bx + A01 * by + A02 * bz + A03;
    float y = A10 * bx + A11 * by + A12 * bz + A13;
    float z = A20 * bx + A21 * by + A22 * bz + A23 + 1.0f;   // +1 pad offset

    float x0f = floorf(x), y0f = floorf(y), z0f = floorf(z);
    float wx = x - x0f, wy = y - y0f, wz = z - z0f;
    int x0 = (int)x0f, y0 = (int)y0f, z0 = (int)z0f;

    int base_b = b * HH;

    #pragma unroll
    for (int dx = 0; dx < 2; dx++) {
        int xi = x0 + dx;
        if (xi < 0 || xi >= HH) continue;
        float fwx = dx ? wx : (1.0f - wx);
        #pragma unroll
        for (int dy = 0; dy < 2; dy++) {
            int yi = y0 + dy;
            if (yi < 0 || yi >= WW) continue;
            float fwy = dy ? wy : (1.0f - wy);
            float fwxy = fwx * fwy;
            int lin_xy = ((base_b + xi) * WW + yi) * ZV;
            #pragma unroll
            for (int dz = 0; dz < 2; dz++) {
                int zi = z0 + dz;
                if (zi < 0 || zi >= ZV) continue;
                float ww = fwxy * (dz ? wz : (1.0f - wz));
                int lin = lin_xy + zi;
                red_add_v2(&g_acc[2 * lin], ww * v, ww);
            }
        }
    }
}

// ---------------------------------------------------------------------------
// Finalize: crop z[1:1+ZS], split interleaved N/D, apply where(D<=0, 1, D).
// Output layout: N block (B,H,W,ZS) then D block (B,H,W,ZS).
// ---------------------------------------------------------------------------
__global__ __launch_bounds__(256) void finalize_kernel(float* __restrict__ out)
{
    int j = blockIdx.x * blockDim.x + threadIdx.x;
    if (j >= OUT_PER) return;

    int z = j % ZS;
    int hwb = j / ZS;                 // (b*H+h)*W + w
    int lin = hwb * ZV + (z + 1);

    float2 nd = *reinterpret_cast<const float2*>(&g_acc[2 * lin]);

    out[j]           = nd.x;
    out[OUT_PER + j] = (nd.y > 0.0f) ? nd.y : 1.0f;
}

// ---------------------------------------------------------------------------
extern "C" void kernel_launch(void* const* d_in, const int* in_sizes, int n_in,
                              void* d_out, int out_size)
{
    const float* vol = (const float*)d_in[0];
    const float* trf = (const float*)d_in[1];
    float* out = (float*)d_out;

    void* acc_ptr = nullptr;
    cudaGetSymbolAddress(&acc_ptr, g_acc);
    cudaMemsetAsync(acc_ptr, 0, sizeof(float) * 2 * VOXELS, 0);

    {
        int threads = 256;
        int blocks = (PIXELS + threads - 1) / threads;
        splat_kernel<<<blocks, threads>>>(vol, trf);
    }
    {
        int threads = 256;
        int blocks = (OUT_PER + threads - 1) / threads;
        finalize_kernel<<<blocks, threads>>>(out);
    }
}